// round 16
// baseline (speedup 1.0000x reference)
#include <cuda_runtime.h>
#include <cuda_fp16.h>
#include <cstdint>
#include <math.h>

#define NB 8
#define NT 2048
#define NC 512
#define SCALE 0.04419417382415922f   // 1/sqrt(512)

// ---------------- scratch (__device__ globals; allocation-free rule) --------
__device__ __align__(256) __half g_xr [NB * NT * NC];          // x, fp16
__device__ __align__(256) __half g_wT [3 * NC * NC];           // WqT|WkT|WvT fp16
__device__ __align__(256) __half g_qk [(size_t)NB * NT * 1024];// [b·t][q 512 | k 512]
__device__ __align__(256) __half g_vT [NB * NT * NC];          // fp16 [b][c][t], pre-normalized
__device__ __align__(256) __half g_p  [(size_t)NB * NT * NT];  // P=exp [b][t][s] fp16
__device__ __align__(256) float  g_bqk[1024];                  // bq|bk concat
__device__ __align__(256) float  g_zpart[16 * NB * NT];        // per-t-tile Z partials

// ---------------- helpers ---------------------------------------------------
__device__ __forceinline__ uint32_t smem_u32(const void* p) {
    uint32_t a;
    asm("{ .reg .u64 t; cvta.to.shared.u64 t, %1; cvt.u32.u64 %0, t; }" : "=r"(a) : "l"(p));
    return a;
}
__device__ __forceinline__ void mma_f16(float* c, const uint32_t* a, const uint32_t* b) {
    asm volatile(
        "mma.sync.aligned.m16n8k16.row.col.f32.f16.f16.f32 "
        "{%0,%1,%2,%3}, {%4,%5,%6,%7}, {%8,%9}, {%0,%1,%2,%3};"
        : "+f"(c[0]), "+f"(c[1]), "+f"(c[2]), "+f"(c[3])
        : "r"(a[0]), "r"(a[1]), "r"(a[2]), "r"(a[3]), "r"(b[0]), "r"(b[1]));
}
__device__ __forceinline__ void ldsm4(uint32_t* r, uint32_t addr) {
    asm volatile("ldmatrix.sync.aligned.m8n8.x4.shared.b16 {%0,%1,%2,%3}, [%4];"
                 : "=r"(r[0]), "=r"(r[1]), "=r"(r[2]), "=r"(r[3]) : "r"(addr));
}
__device__ __forceinline__ void cp16(uint32_t dst, const void* src) {
    asm volatile("cp.async.cg.shared.global [%0], [%1], 16;" :: "r"(dst), "l"(src));
}
#define CP_COMMIT() asm volatile("cp.async.commit_group;" ::: "memory")
#define CP_WAIT1()  asm volatile("cp.async.wait_group 1;" ::: "memory")

// ---------------------------------------------------------------------------
// fp16-input / fp32-accum GEMM via mma.sync m16n8k16 + ldmatrix fragments:
//   D[m][n] = sum_k A[m][k] * B[n][k]   (A,B __half, k-contiguous)
// CTA tile 128x128, BK=64 halfs, 128 threads, warp tile 64x64 (2x2 warps),
// 2 CTAs/SM.  3-stage cp.async(16B) pipeline; stage (32KB) = A 16KB + B 16KB;
//   16B chunk c of row r at r*128 + ((c^(r&7))<<4).
// Per iter: wait_group(1), sync, issue load c+2 (slot freed at iter c-1), commit.
// OUT: 0 = fp32 C; 1 = fp16 C; 2 = attention-P epilogue (exp+mask+Z partials).
// SCALEN: V-proj mode — compute zinv for this CTA's 128 tokens in the
//   prologue (sum of zpart rows j0..15 + rcp, stored in smem past the stages)
//   and multiply outputs by it before the fp16 store.
// CKLIM: kend = min(K, m0+128), REVERSED y-order.  BATCHN: b = n>>11.
// BIASN: bias[n].  BIASM: bias[m].
// ---------------------------------------------------------------------------
template<bool BIASN, bool BIASM, bool CKLIM, int OUT, bool BATCHN, bool SCALEN>
__global__ __launch_bounds__(128, 2)
void gemm_h(const __half* __restrict__ Ag, const __half* __restrict__ Bg,
            const float* __restrict__ bias, const float* __restrict__ Zp_in,
            float* __restrict__ Cf, __half* __restrict__ Ch, float* __restrict__ Zp,
            int lda, int ldb, int ldc, int Ktot,
            size_t sA, size_t sB, size_t sC)
{
    extern __shared__ char smem[];
    const int m0 = CKLIM ? (int)(gridDim.y - 1 - blockIdx.y) * 128
                         : (int)blockIdx.y * 128;
    const int n0 = blockIdx.x * 128;
    if (OUT == 2 && n0 >= m0 + 128) return;   // causal: no s<=t in tile

    const __half* A = Ag + (size_t)blockIdx.z * sA;
    const __half* B = Bg + (size_t)blockIdx.z * sB;

    const int tid = threadIdx.x;
    const int lane = tid & 31;
    const int wid = tid >> 5;              // 0..3
    const int warp_m = (wid & 1) * 64;
    const int warp_n = (wid >> 1) * 64;
    const int g  = lane >> 2;    // 0..7
    const int tg = lane & 3;     // 0..3
    const uint32_t smem_u = smem_u32(smem);
    float* zinv_s = (float*)(smem + 3 * 32768);   // [128], SCALEN only

    // ---- ldmatrix per-lane addresses ----
    const int low = lane & 7;
    const int a_hi  = lane >> 4;          // chunk +0/+1
    const int a_mid = (lane >> 3) & 1;    // row +0/+8
    uint32_t arow[4];
#pragma unroll
    for (int mt = 0; mt < 4; mt++)
        arow[mt] = (uint32_t)(warp_m + mt * 16 + a_mid * 8 + low) * 128;
    uint32_t cswzA[4];
#pragma unroll
    for (int ks = 0; ks < 4; ks++)
        cswzA[ks] = (uint32_t)(((2 * ks + a_hi) ^ low) << 4);
    const int b_sel = lane >> 3;          // 0..3
    const int b_hi  = b_sel & 1;          // chunk +0/+1
    const int b_mid = b_sel >> 1;         // row +0/+8
    uint32_t brow[4];
#pragma unroll
    for (int np = 0; np < 4; np++)
        brow[np] = 16384u + (uint32_t)(warp_n + np * 16 + b_mid * 8 + low) * 128;
    uint32_t cswzB[4];
#pragma unroll
    for (int ks = 0; ks < 4; ks++)
        cswzB[ks] = (uint32_t)(((2 * ks + b_hi) ^ low) << 4);

    // loader: lc = 16B chunk 0..7 within row, lr = row base 0..15 (+16i)
    const int lc = tid & 7;
    const int lr = tid >> 3;

    float acc[4][8][4];
#pragma unroll
    for (int mt = 0; mt < 4; mt++)
#pragma unroll
        for (int nt = 0; nt < 8; nt++)
#pragma unroll
            for (int r = 0; r < 4; r++) acc[mt][nt][r] = 0.f;

    const int kend = CKLIM ? min(Ktot, m0 + 128) : Ktot;
    const int nch = kend >> 6;   // BK = 64 halfs; >= 2 always here

    auto load_stage = [&](int slot, int chunk) {
        const uint32_t sbase = smem_u + (uint32_t)slot * 32768u;
        const int k0 = (chunk << 6) + lc * 8;
#pragma unroll
        for (int i = 0; i < 8; i++) {   // A: 128 rows
            const int r = lr + i * 16;
            const uint32_t off = (uint32_t)r * 128 + ((uint32_t)(lc ^ (r & 7)) << 4);
            cp16(sbase + off, A + (size_t)(m0 + r) * lda + k0);
        }
#pragma unroll
        for (int i = 0; i < 8; i++) {   // B: 128 rows
            const int r = lr + i * 16;
            const uint32_t off = (uint32_t)r * 128 + ((uint32_t)(lc ^ (r & 7)) << 4);
            cp16(sbase + 16384u + off, B + (size_t)(n0 + r) * ldb + k0);
        }
    };

    // prologue: stages 0,1
#pragma unroll
    for (int s = 0; s < 2; s++) {
        if (s < nch) load_stage(s, s);
        CP_COMMIT();
    }

    // SCALEN: compute 1/Z for this CTA's 128 tokens while cp.async is in flight.
    if (SCALEN) {
        const int token = n0 + tid;               // global token index
        const int j0 = (token & (NT - 1)) >> 7;   // first t-tile writing this s
        float s = 0.f;
        for (int j = j0; j < 16; j++) s += Zp_in[(size_t)j * (NB * NT) + token];
        zinv_s[tid] = 1.f / s;
        __syncthreads();
    }

    for (int c = 0; c < nch; c++) {
        CP_WAIT1();          // commits = c+2 ; completed >= c+1  => chunk c ready
        __syncthreads();     // all warps done with chunk c-1 (slot c+2 target)
        if (c + 2 < nch) load_stage((c + 2) % 3, c + 2);
        CP_COMMIT();

        const uint32_t su = smem_u + (uint32_t)(c % 3) * 32768u;
#pragma unroll
        for (int ks = 0; ks < 4; ks++) {
            uint32_t a[4][4], b[8][2];
#pragma unroll
            for (int mt = 0; mt < 4; mt++)
                ldsm4(a[mt], su + arow[mt] + cswzA[ks]);
#pragma unroll
            for (int np = 0; np < 4; np++) {
                uint32_t t4[4];
                ldsm4(t4, su + brow[np] + cswzB[ks]);
                b[2 * np][0]     = t4[0];
                b[2 * np][1]     = t4[1];
                b[2 * np + 1][0] = t4[2];
                b[2 * np + 1][1] = t4[3];
            }
#pragma unroll
            for (int mt = 0; mt < 4; mt++)
#pragma unroll
                for (int nt = 0; nt < 8; nt++)
                    mma_f16(acc[mt][nt], a[mt], b[nt]);
        }
    }

    // ---- epilogue ----
    int nbase;
    size_t cofs;
    if (BATCHN) {
        cofs = (size_t)(n0 >> 11) * sC;
        nbase = n0 & 2047;
    } else {
        cofs = (size_t)blockIdx.z * sC;
        nbase = n0;
    }

    if (OUT == 2) {
        float zacc0[8], zacc1[8];
#pragma unroll
        for (int nt = 0; nt < 8; nt++) { zacc0[nt] = 0.f; zacc1[nt] = 0.f; }
#pragma unroll
        for (int mt = 0; mt < 4; mt++) {
            const int m = m0 + warp_m + mt * 16 + g;   // t
#pragma unroll
            for (int nt = 0; nt < 8; nt++) {
                const int n = n0 + warp_n + nt * 8 + tg * 2;   // s
                const float e00 = (n     <= m)     ? __expf(acc[mt][nt][0] * SCALE) : 0.f;
                const float e01 = (n + 1 <= m)     ? __expf(acc[mt][nt][1] * SCALE) : 0.f;
                const float e10 = (n     <= m + 8) ? __expf(acc[mt][nt][2] * SCALE) : 0.f;
                const float e11 = (n + 1 <= m + 8) ? __expf(acc[mt][nt][3] * SCALE) : 0.f;
                zacc0[nt] += e00 + e10;
                zacc1[nt] += e01 + e11;
                __half* crow = Ch + cofs + (size_t)m * ldc + n;
                *(__half2*)crow = __floats2half2_rn(e00, e01);
                *(__half2*)(crow + (size_t)8 * ldc) = __floats2half2_rn(e10, e11);
            }
        }
        __syncthreads();                       // stage smem now reusable
        float* zp = (float*)smem;              // [2][128]
#pragma unroll
        for (int nt = 0; nt < 8; nt++) {
            float s0 = zacc0[nt], s1 = zacc1[nt];
#pragma unroll
            for (int mk = 16; mk >= 4; mk >>= 1) {
                s0 += __shfl_xor_sync(0xffffffffu, s0, mk);
                s1 += __shfl_xor_sync(0xffffffffu, s1, mk);
            }
            if (lane < 4) {
                const int sl = warp_n + nt * 8 + tg * 2;
                zp[(wid & 1) * 128 + sl]     = s0;
                zp[(wid & 1) * 128 + sl + 1] = s1;
            }
        }
        __syncthreads();
        Zp[(size_t)(m0 >> 7) * (NB * NT) + (size_t)blockIdx.z * NT + n0 + tid]
            = zp[tid] + zp[128 + tid];
        return;
    }

#pragma unroll
    for (int mt = 0; mt < 4; mt++) {
        const int m = m0 + warp_m + mt * 16 + g;
#pragma unroll
        for (int nt = 0; nt < 8; nt++) {
            const int n = nbase + warp_n + nt * 8 + tg * 2;
            float v00 = acc[mt][nt][0], v01 = acc[mt][nt][1];
            float v10 = acc[mt][nt][2], v11 = acc[mt][nt][3];
            if (BIASN) {
                const float b0 = bias[n0 - nbase + n], b1 = bias[n0 - nbase + n + 1];
                v00 += b0; v01 += b1;
                v10 += b0; v11 += b1;
            }
            if (BIASM) {
                const float bm0 = bias[m], bm1 = bias[m + 8];
                v00 += bm0; v01 += bm0;
                v10 += bm1; v11 += bm1;
            }
            if (SCALEN) {
                const int ln = warp_n + nt * 8 + tg * 2;   // local token 0..127
                const float z0 = zinv_s[ln], z1 = zinv_s[ln + 1];
                v00 *= z0; v01 *= z1;
                v10 *= z0; v11 *= z1;
            }
            if (OUT == 1) {
                __half* crow = Ch + cofs + (size_t)m * ldc + n;
                *(__half2*)crow = __floats2half2_rn(v00, v01);
                *(__half2*)(crow + (size_t)8 * ldc) = __floats2half2_rn(v10, v11);
            } else {
                float* crow = Cf + cofs + (size_t)m * ldc + n;
                *(float2*)crow = make_float2(v00, v01);
                *(float2*)(crow + (size_t)8 * ldc) = make_float2(v10, v11);
            }
        }
    }
}

// ---------------------------------------------------------------------------
// Merged prep: z=0 -> x->fp16 + out[,0:512]=x (1D over float4s, 64 CTAs/z-slice
// handled via blockIdx.x);  z=1..3 -> weight transpose W(z-1);  z=4 -> biases.
// Launched as grid(256, 16, 5): z=0 uses x*y flattened; z=1..3 use (x<16,y).
// ---------------------------------------------------------------------------
__global__ void prep_all(const float4* __restrict__ xin, __half2* __restrict__ xh2,
                         float4* __restrict__ out4,
                         const float* __restrict__ W0, const float* __restrict__ W1,
                         const float* __restrict__ W2, const float* __restrict__ bq,
                         const float* __restrict__ bk, __half* __restrict__ WT,
                         float* __restrict__ bqk)
{
    if (blockIdx.z == 0) {
        // 256 x 16 CTAs x 256 thr = 1,048,576 >= n4 = 2,097,152/2 ... use 2 f4/thr
        const int i0 = ((blockIdx.y * 256 + blockIdx.x) * 256 + threadIdx.x) * 2;
        const int n4 = NB * NT * NC / 4;
#pragma unroll
        for (int u = 0; u < 2; u++) {
            const int i = i0 + u;
            if (i >= n4) break;
            const float4 v = xin[i];
            xh2[2 * i + 0] = __floats2half2_rn(v.x, v.y);
            xh2[2 * i + 1] = __floats2half2_rn(v.z, v.w);
            const size_t row = (size_t)i >> 7;
            const size_t col = (size_t)i & 127;
            out4[row * 256 + col] = v;
        }
        return;
    }
    if (blockIdx.z == 4) {
        if (blockIdx.y == 0 && blockIdx.x < 4) {
            const int i = blockIdx.x * 256 + threadIdx.x;
            bqk[i] = (i < 512) ? bq[i] : bk[i - 512];
        }
        return;
    }
    if (blockIdx.x >= 16) return;
    const int wsel = blockIdx.z - 1;
    const float* W = (wsel == 0) ? W0 : (wsel == 1) ? W1 : W2;
    __half* WTo = WT + (size_t)wsel * NC * NC;
    __shared__ float tile[32][33];
    const int tx = threadIdx.x & 31, ty = threadIdx.x >> 5;
    const int c0 = blockIdx.x * 32, r0 = blockIdx.y * 32;
#pragma unroll
    for (int r = 0; r < 4; r++)
        tile[ty + r * 8][tx] = W[(size_t)(r0 + ty + r * 8) * NC + c0 + tx];
    __syncthreads();
#pragma unroll
    for (int r = 0; r < 4; r++)
        WTo[(size_t)(c0 + ty + r * 8) * NC + r0 + tx] = __float2half_rn(tile[tx][ty + r * 8]);
}

// ---------------------------------------------------------------------------
extern "C" void kernel_launch(void* const* d_in, const int* in_sizes, int n_in,
                              void* d_out, int out_size)
{
    const float* x  = (const float*)d_in[0];
    const float* Wq = (const float*)d_in[1];
    const float* bq = (const float*)d_in[2];
    const float* Wk = (const float*)d_in[3];
    const float* bk = (const float*)d_in[4];
    const float* Wv = (const float*)d_in[5];
    const float* bv = (const float*)d_in[6];
    float* out = (float*)d_out;

    __half *xr, *wT, *qk, *vT, *p;
    float *bqk, *zpart;
    cudaGetSymbolAddress((void**)&xr,    g_xr);
    cudaGetSymbolAddress((void**)&wT,    g_wT);
    cudaGetSymbolAddress((void**)&qk,    g_qk);
    cudaGetSymbolAddress((void**)&vT,    g_vT);
    cudaGetSymbolAddress((void**)&p,     g_p);
    cudaGetSymbolAddress((void**)&bqk,   g_bqk);
    cudaGetSymbolAddress((void**)&zpart, g_zpart);

    const int SMEM  = 3 * 32768;        // 98304 per CTA; 2 CTAs/SM
    const int SMEMZ = 3 * 32768 + 512;  // + zinv_s[128] for SCALEN path
    cudaFuncSetAttribute(gemm_h<true,  false, false, 1, false, false>, cudaFuncAttributeMaxDynamicSharedMemorySize, SMEM);
    cudaFuncSetAttribute(gemm_h<false, true,  false, 1, true,  true >, cudaFuncAttributeMaxDynamicSharedMemorySize, SMEMZ);
    cudaFuncSetAttribute(gemm_h<false, false, false, 2, false, false>, cudaFuncAttributeMaxDynamicSharedMemorySize, SMEM);
    cudaFuncSetAttribute(gemm_h<false, false, true,  0, false, false>, cudaFuncAttributeMaxDynamicSharedMemorySize, SMEM);

    const size_t strQK  = (size_t)NT * 1024;
    const size_t strLG  = (size_t)NT * NT;
    const size_t strOUT = (size_t)NT * (2 * NC);

    // 0) merged prep: x->fp16 (+copy to out), W transposes, bias concat
    prep_all<<<dim3(256, 16, 5), 256>>>(
        (const float4*)x, (__half2*)xr, (float4*)out,
        Wq, Wk, Wv, bq, bk, wT, bqk);

    // 1) merged Q|K projection: qk[b·t][0:512]=q, [512:1024]=k  (N=1024)
    {
        dim3 grid(1024 / 128, (NB * NT) / 128, 1);
        gemm_h<true, false, false, 1, false, false><<<grid, 128, SMEM>>>(
            xr, wT, bqk, nullptr, nullptr, qk, nullptr, NC, NC, 1024, NC, 0, 0, 0);
    }

    // 2) P[b][t][s] = (s<=t) ? exp(q.k * SCALE) : 0  (fp16) + Z partials
    //    (zpart slots [j][b][s] with j >= s>>7 are all written; others unread)
    {
        dim3 grid(NT / 128, NT / 128, NB);   // m = t (A = q), n = s (B = k)
        gemm_h<false, false, false, 2, false, false><<<grid, 128, SMEM>>>(
            qk, qk + 512, nullptr, nullptr, nullptr, p, zpart, 1024, 1024, NT, NC,
            strQK, strQK, strLG);
    }

    // 3) V projection, transposed + pre-normalized (zinv computed inline):
    //    vT[b][c][t] = (sum_k WvT[c][k] x[b,t,k] + bv[c]) / Z[b][t]
    {
        dim3 grid((NB * NT) / 128, NC / 128, 1);   // n = global token, m = channel
        gemm_h<false, true, false, 1, true, true><<<grid, 128, SMEMZ>>>(
            wT + 2 * NC * NC, xr, bv, zpart, nullptr, vT, nullptr,
            NC, NC, NT, NC, 0, 0, (size_t)NC * NT);
    }

    // 4) read[b][t][v] = sum_s P[b,t,s] * vT[b,v,s]  -> out[..., 512:1024]
    {
        dim3 grid(NC / 128, NT / 128, NB);
        gemm_h<false, false, true, 0, false, false><<<grid, 128, SMEM>>>(
            p, vT, nullptr, nullptr, out + NC, nullptr, nullptr, NT, NT, 2 * NC, NT,
            strLG, (size_t)NC * NT, strOUT);
    }
}

// round 17
// speedup vs baseline: 1.0023x; 1.0023x over previous
#include <cuda_runtime.h>
#include <cuda_fp16.h>
#include <cstdint>
#include <math.h>

#define NB 8
#define NT 2048
#define NC 512
#define SCALE 0.04419417382415922f   // 1/sqrt(512)

// ---------------- scratch (__device__ globals; allocation-free rule) --------
__device__ __align__(256) __half g_xr [NB * NT * NC];          // x, fp16
__device__ __align__(256) __half g_wT [3 * NC * NC];           // WqT|WkT|WvT fp16
__device__ __align__(256) __half g_qk [(size_t)NB * NT * 1024];// [b·t][q 512 | k 512]
__device__ __align__(256) __half g_vT [NB * NT * NC];          // fp16 [b][c][t], pre-normalized
__device__ __align__(256) __half g_p  [(size_t)NB * NT * NT];  // P=exp [b][t][s] fp16
__device__ __align__(256) float  g_bqk[1024];                  // bq|bk concat
__device__ __align__(256) float  g_zpart[16 * NB * NT];        // per-t-tile Z partials
__device__ __align__(256) float  g_zinv [NB * NT];             // 1/Z[s]

// ---------------- helpers ---------------------------------------------------
__device__ __forceinline__ uint32_t smem_u32(const void* p) {
    uint32_t a;
    asm("{ .reg .u64 t; cvta.to.shared.u64 t, %1; cvt.u32.u64 %0, t; }" : "=r"(a) : "l"(p));
    return a;
}
__device__ __forceinline__ void mma_f16(float* c, const uint32_t* a, const uint32_t* b) {
    asm volatile(
        "mma.sync.aligned.m16n8k16.row.col.f32.f16.f16.f32 "
        "{%0,%1,%2,%3}, {%4,%5,%6,%7}, {%8,%9}, {%0,%1,%2,%3};"
        : "+f"(c[0]), "+f"(c[1]), "+f"(c[2]), "+f"(c[3])
        : "r"(a[0]), "r"(a[1]), "r"(a[2]), "r"(a[3]), "r"(b[0]), "r"(b[1]));
}
__device__ __forceinline__ void ldsm4(uint32_t* r, uint32_t addr) {
    asm volatile("ldmatrix.sync.aligned.m8n8.x4.shared.b16 {%0,%1,%2,%3}, [%4];"
                 : "=r"(r[0]), "=r"(r[1]), "=r"(r[2]), "=r"(r[3]) : "r"(addr));
}
__device__ __forceinline__ void cp16(uint32_t dst, const void* src) {
    asm volatile("cp.async.cg.shared.global [%0], [%1], 16;" :: "r"(dst), "l"(src));
}
#define CP_COMMIT() asm volatile("cp.async.commit_group;" ::: "memory")
#define CP_WAIT1()  asm volatile("cp.async.wait_group 1;" ::: "memory")

// ---------------------------------------------------------------------------
// fp16-input / fp32-accum GEMM via mma.sync m16n8k16 + ldmatrix fragments:
//   D[m][n] = sum_k A[m][k] * B[n][k]   (A,B __half, k-contiguous)
// CTA tile 128x128, BK=64 halfs, 128 threads, warp tile 64x64 (2x2 warps),
// 2 CTAs/SM.  3-stage cp.async(16B) pipeline; stage (32KB) = A 16KB + B 16KB;
//   16B chunk c of row r at r*128 + ((c^(r&7))<<4).
// Per iter: wait_group(1), sync, issue load c+2 (slot freed at iter c-1), commit.
// OUT: 0 = fp32 C; 1 = fp16 C; 2 = attention-P epilogue (exp+mask+Z partials),
//   launched on a TRIANGULAR grid: blockIdx.x = linear lower-triangle tile id,
//   decoded to (t-tile, s-tile); all launched CTAs are active and equal-cost.
// SCALEN: multiply output by Zs[global n] before store (fp16 path).
// CKLIM: kend = min(K, m0+128), REVERSED y-order.  BATCHN: b = n>>11.
// BIASN: bias[n].  BIASM: bias[m].
// ---------------------------------------------------------------------------
template<bool BIASN, bool BIASM, bool CKLIM, int OUT, bool BATCHN, bool SCALEN>
__global__ __launch_bounds__(128, 2)
void gemm_h(const __half* __restrict__ Ag, const __half* __restrict__ Bg,
            const float* __restrict__ bias, const float* __restrict__ Zs,
            float* __restrict__ Cf, __half* __restrict__ Ch, float* __restrict__ Zp,
            int lda, int ldb, int ldc, int Ktot,
            size_t sA, size_t sB, size_t sC)
{
    extern __shared__ char smem[];
    int m0, n0;
    if (OUT == 2) {
        // triangular decode: L -> (ti, si), si <= ti, 136 tiles per batch
        const int L = blockIdx.x;
        int ti = (int)((__fsqrt_rn(8.f * (float)L + 1.f) - 1.f) * 0.5f);
        if ((ti + 1) * (ti + 2) / 2 <= L) ti++;
        if (ti * (ti + 1) / 2 > L) ti--;
        const int si = L - ti * (ti + 1) / 2;
        m0 = ti * 128;
        n0 = si * 128;
    } else {
        m0 = CKLIM ? (int)(gridDim.y - 1 - blockIdx.y) * 128
                   : (int)blockIdx.y * 128;
        n0 = blockIdx.x * 128;
    }

    const __half* A = Ag + (size_t)blockIdx.z * sA;
    const __half* B = Bg + (size_t)blockIdx.z * sB;

    const int tid = threadIdx.x;
    const int lane = tid & 31;
    const int wid = tid >> 5;              // 0..3
    const int warp_m = (wid & 1) * 64;
    const int warp_n = (wid >> 1) * 64;
    const int g  = lane >> 2;    // 0..7
    const int tg = lane & 3;     // 0..3
    const uint32_t smem_u = smem_u32(smem);

    // ---- ldmatrix per-lane addresses ----
    const int low = lane & 7;
    const int a_hi  = lane >> 4;          // chunk +0/+1
    const int a_mid = (lane >> 3) & 1;    // row +0/+8
    uint32_t arow[4];
#pragma unroll
    for (int mt = 0; mt < 4; mt++)
        arow[mt] = (uint32_t)(warp_m + mt * 16 + a_mid * 8 + low) * 128;
    uint32_t cswzA[4];
#pragma unroll
    for (int ks = 0; ks < 4; ks++)
        cswzA[ks] = (uint32_t)(((2 * ks + a_hi) ^ low) << 4);
    const int b_sel = lane >> 3;          // 0..3
    const int b_hi  = b_sel & 1;          // chunk +0/+1
    const int b_mid = b_sel >> 1;         // row +0/+8
    uint32_t brow[4];
#pragma unroll
    for (int np = 0; np < 4; np++)
        brow[np] = 16384u + (uint32_t)(warp_n + np * 16 + b_mid * 8 + low) * 128;
    uint32_t cswzB[4];
#pragma unroll
    for (int ks = 0; ks < 4; ks++)
        cswzB[ks] = (uint32_t)(((2 * ks + b_hi) ^ low) << 4);

    // loader: lc = 16B chunk 0..7 within row, lr = row base 0..15 (+16i)
    const int lc = tid & 7;
    const int lr = tid >> 3;

    float acc[4][8][4];
#pragma unroll
    for (int mt = 0; mt < 4; mt++)
#pragma unroll
        for (int nt = 0; nt < 8; nt++)
#pragma unroll
            for (int r = 0; r < 4; r++) acc[mt][nt][r] = 0.f;

    const int kend = CKLIM ? min(Ktot, m0 + 128) : Ktot;
    const int nch = kend >> 6;   // BK = 64 halfs; >= 2 always here

    auto load_stage = [&](int slot, int chunk) {
        const uint32_t sbase = smem_u + (uint32_t)slot * 32768u;
        const int k0 = (chunk << 6) + lc * 8;
#pragma unroll
        for (int i = 0; i < 8; i++) {   // A: 128 rows
            const int r = lr + i * 16;
            const uint32_t off = (uint32_t)r * 128 + ((uint32_t)(lc ^ (r & 7)) << 4);
            cp16(sbase + off, A + (size_t)(m0 + r) * lda + k0);
        }
#pragma unroll
        for (int i = 0; i < 8; i++) {   // B: 128 rows
            const int r = lr + i * 16;
            const uint32_t off = (uint32_t)r * 128 + ((uint32_t)(lc ^ (r & 7)) << 4);
            cp16(sbase + 16384u + off, B + (size_t)(n0 + r) * ldb + k0);
        }
    };

    // prologue: stages 0,1
#pragma unroll
    for (int s = 0; s < 2; s++) {
        if (s < nch) load_stage(s, s);
        CP_COMMIT();
    }

    for (int c = 0; c < nch; c++) {
        CP_WAIT1();          // commits = c+2 ; completed >= c+1  => chunk c ready
        __syncthreads();     // all warps done with chunk c-1 (slot c+2 target)
        if (c + 2 < nch) load_stage((c + 2) % 3, c + 2);
        CP_COMMIT();

        const uint32_t su = smem_u + (uint32_t)(c % 3) * 32768u;
#pragma unroll
        for (int ks = 0; ks < 4; ks++) {
            uint32_t a[4][4], b[8][2];
#pragma unroll
            for (int mt = 0; mt < 4; mt++)
                ldsm4(a[mt], su + arow[mt] + cswzA[ks]);
#pragma unroll
            for (int np = 0; np < 4; np++) {
                uint32_t t4[4];
                ldsm4(t4, su + brow[np] + cswzB[ks]);
                b[2 * np][0]     = t4[0];
                b[2 * np][1]     = t4[1];
                b[2 * np + 1][0] = t4[2];
                b[2 * np + 1][1] = t4[3];
            }
#pragma unroll
            for (int mt = 0; mt < 4; mt++)
#pragma unroll
                for (int nt = 0; nt < 8; nt++)
                    mma_f16(acc[mt][nt], a[mt], b[nt]);
        }
    }

    // ---- epilogue ----
    int nbase;
    size_t cofs;
    if (BATCHN) {
        cofs = (size_t)(n0 >> 11) * sC;
        nbase = n0 & 2047;
    } else {
        cofs = (size_t)blockIdx.z * sC;
        nbase = n0;
    }

    if (OUT == 2) {
        float zacc0[8], zacc1[8];
#pragma unroll
        for (int nt = 0; nt < 8; nt++) { zacc0[nt] = 0.f; zacc1[nt] = 0.f; }
#pragma unroll
        for (int mt = 0; mt < 4; mt++) {
            const int m = m0 + warp_m + mt * 16 + g;   // t
#pragma unroll
            for (int nt = 0; nt < 8; nt++) {
                const int n = n0 + warp_n + nt * 8 + tg * 2;   // s
                const float e00 = (n     <= m)     ? __expf(acc[mt][nt][0] * SCALE) : 0.f;
                const float e01 = (n + 1 <= m)     ? __expf(acc[mt][nt][1] * SCALE) : 0.f;
                const float e10 = (n     <= m + 8) ? __expf(acc[mt][nt][2] * SCALE) : 0.f;
                const float e11 = (n + 1 <= m + 8) ? __expf(acc[mt][nt][3] * SCALE) : 0.f;
                zacc0[nt] += e00 + e10;
                zacc1[nt] += e01 + e11;
                __half* crow = Ch + cofs + (size_t)m * ldc + n;
                *(__half2*)crow = __floats2half2_rn(e00, e01);
                *(__half2*)(crow + (size_t)8 * ldc) = __floats2half2_rn(e10, e11);
            }
        }
        __syncthreads();                       // stage smem now reusable
        float* zp = (float*)smem;              // [2][128]
#pragma unroll
        for (int nt = 0; nt < 8; nt++) {
            float s0 = zacc0[nt], s1 = zacc1[nt];
#pragma unroll
            for (int mk = 16; mk >= 4; mk >>= 1) {
                s0 += __shfl_xor_sync(0xffffffffu, s0, mk);
                s1 += __shfl_xor_sync(0xffffffffu, s1, mk);
            }
            if (lane < 4) {
                const int sl = warp_n + nt * 8 + tg * 2;
                zp[(wid & 1) * 128 + sl]     = s0;
                zp[(wid & 1) * 128 + sl + 1] = s1;
            }
        }
        __syncthreads();
        Zp[(size_t)(m0 >> 7) * (NB * NT) + (size_t)blockIdx.z * NT + n0 + tid]
            = zp[tid] + zp[128 + tid];
        return;
    }

#pragma unroll
    for (int mt = 0; mt < 4; mt++) {
        const int m = m0 + warp_m + mt * 16 + g;
#pragma unroll
        for (int nt = 0; nt < 8; nt++) {
            const int n = nbase + warp_n + nt * 8 + tg * 2;
            float v00 = acc[mt][nt][0], v01 = acc[mt][nt][1];
            float v10 = acc[mt][nt][2], v11 = acc[mt][nt][3];
            if (BIASN) {
                const float b0 = bias[n0 - nbase + n], b1 = bias[n0 - nbase + n + 1];
                v00 += b0; v01 += b1;
                v10 += b0; v11 += b1;
            }
            if (BIASM) {
                const float bm0 = bias[m], bm1 = bias[m + 8];
                v00 += bm0; v01 += bm0;
                v10 += bm1; v11 += bm1;
            }
            if (SCALEN) {
                const int gn = n0 - nbase + n;   // global token index
                const float z0 = Zs[gn], z1 = Zs[gn + 1];
                v00 *= z0; v01 *= z1;
                v10 *= z0; v11 *= z1;
            }
            if (OUT == 1) {
                __half* crow = Ch + cofs + (size_t)m * ldc + n;
                *(__half2*)crow = __floats2half2_rn(v00, v01);
                *(__half2*)(crow + (size_t)8 * ldc) = __floats2half2_rn(v10, v11);
            } else {
                float* crow = Cf + cofs + (size_t)m * ldc + n;
                *(float2*)crow = make_float2(v00, v01);
                *(float2*)(crow + (size_t)8 * ldc) = make_float2(v10, v11);
            }
        }
    }
}

// ---------------------------------------------------------------------------
// x -> fp16 copy, fused with out[..., 0:512] = x
// ---------------------------------------------------------------------------
__global__ void cvt_x(const float4* __restrict__ in, __half2* __restrict__ xh2,
                      float4* __restrict__ out4, int n4)
{
    const int i = blockIdx.x * blockDim.x + threadIdx.x;
    if (i >= n4) return;
    const float4 v = in[i];
    xh2[2 * i + 0] = __floats2half2_rn(v.x, v.y);
    xh2[2 * i + 1] = __floats2half2_rn(v.z, v.w);
    const size_t row = (size_t)i >> 7;
    const size_t col = (size_t)i & 127;
    out4[row * 256 + col] = v;
}

// Merged weight transposes (z=0..2) + bias concat (z=3).
__global__ void prep_w(const float* __restrict__ W0, const float* __restrict__ W1,
                       const float* __restrict__ W2, const float* __restrict__ bq,
                       const float* __restrict__ bk, __half* __restrict__ WT,
                       float* __restrict__ bqk)
{
    if (blockIdx.z == 3) {
        if (blockIdx.y == 0 && blockIdx.x < 4) {
            const int i = blockIdx.x * 256 + threadIdx.x;
            bqk[i] = (i < 512) ? bq[i] : bk[i - 512];
        }
        return;
    }
    const float* W = (blockIdx.z == 0) ? W0 : (blockIdx.z == 1) ? W1 : W2;
    __half* WTo = WT + (size_t)blockIdx.z * NC * NC;
    __shared__ float tile[32][33];
    const int tx = threadIdx.x & 31, ty = threadIdx.x >> 5;
    const int c0 = blockIdx.x * 32, r0 = blockIdx.y * 32;
#pragma unroll
    for (int r = 0; r < 4; r++)
        tile[ty + r * 8][tx] = W[(size_t)(r0 + ty + r * 8) * NC + c0 + tx];
    __syncthreads();
#pragma unroll
    for (int r = 0; r < 4; r++)
        WTo[(size_t)(c0 + ty + r * 8) * NC + r0 + tx] = __float2half_rn(tile[tx][ty + r * 8]);
}

// Zinv[b][s] = 1 / sum_j zpart[j][b][s]
__global__ void zinv_k(const float* __restrict__ zp, float* __restrict__ zinv)
{
    const int i = blockIdx.x * 256 + threadIdx.x;
    float s = 0.f;
#pragma unroll
    for (int j = 0; j < 16; j++) s += zp[(size_t)j * (NB * NT) + i];
    zinv[i] = 1.f / s;
}

// ---------------------------------------------------------------------------
extern "C" void kernel_launch(void* const* d_in, const int* in_sizes, int n_in,
                              void* d_out, int out_size)
{
    const float* x  = (const float*)d_in[0];
    const float* Wq = (const float*)d_in[1];
    const float* bq = (const float*)d_in[2];
    const float* Wk = (const float*)d_in[3];
    const float* bk = (const float*)d_in[4];
    const float* Wv = (const float*)d_in[5];
    const float* bv = (const float*)d_in[6];
    float* out = (float*)d_out;

    __half *xr, *wT, *qk, *vT, *p;
    float *bqk, *zpart, *zinv;
    cudaGetSymbolAddress((void**)&xr,    g_xr);
    cudaGetSymbolAddress((void**)&wT,    g_wT);
    cudaGetSymbolAddress((void**)&qk,    g_qk);
    cudaGetSymbolAddress((void**)&vT,    g_vT);
    cudaGetSymbolAddress((void**)&p,     g_p);
    cudaGetSymbolAddress((void**)&bqk,   g_bqk);
    cudaGetSymbolAddress((void**)&zpart, g_zpart);
    cudaGetSymbolAddress((void**)&zinv,  g_zinv);

    const int SMEM = 3 * 32768;   // 98304 per CTA; 2 CTAs/SM
    cudaFuncSetAttribute(gemm_h<true,  false, false, 1, false, false>, cudaFuncAttributeMaxDynamicSharedMemorySize, SMEM);
    cudaFuncSetAttribute(gemm_h<false, true,  false, 1, true,  true >, cudaFuncAttributeMaxDynamicSharedMemorySize, SMEM);
    cudaFuncSetAttribute(gemm_h<false, false, false, 2, false, false>, cudaFuncAttributeMaxDynamicSharedMemorySize, SMEM);
    cudaFuncSetAttribute(gemm_h<false, false, true,  0, false, false>, cudaFuncAttributeMaxDynamicSharedMemorySize, SMEM);

    const size_t strQK  = (size_t)NT * 1024;
    const size_t strLG  = (size_t)NT * NT;
    const size_t strOUT = (size_t)NT * (2 * NC);

    // 0) operand prep + zero Z partials
    cvt_x<<<(NB * NT * NC / 4 + 255) / 256, 256>>>(
        (const float4*)x, (__half2*)xr, (float4*)out, NB * NT * NC / 4);
    prep_w<<<dim3(16, 16, 4), 256>>>(Wq, Wk, Wv, bq, bk, wT, bqk);
    cudaMemsetAsync(zpart, 0, (size_t)16 * NB * NT * sizeof(float), 0);

    // 1) merged Q|K projection: qk[b·t][0:512]=q, [512:1024]=k  (N=1024)
    {
        dim3 grid(1024 / 128, (NB * NT) / 128, 1);
        gemm_h<true, false, false, 1, false, false><<<grid, 128, SMEM>>>(
            xr, wT, bqk, nullptr, nullptr, qk, nullptr, NC, NC, 1024, NC, 0, 0, 0);
    }

    // 2) P[b][t][s] = (s<=t) ? exp(q.k * SCALE) : 0  (fp16) + Z partials
    //    Triangular grid: 136 active lower-triangle tiles per batch.
    {
        dim3 grid(136, 1, NB);
        gemm_h<false, false, false, 2, false, false><<<grid, 128, SMEM>>>(
            qk, qk + 512, nullptr, nullptr, nullptr, p, zpart, 1024, 1024, NT, NC,
            strQK, strQK, strLG);
    }

    // 3) Z reduce -> zinv
    zinv_k<<<NB * NT / 256, 256>>>(zpart, zinv);

    // 4) V projection, transposed + pre-normalized:
    //    vT[b][c][t] = (sum_k WvT[c][k] x[b,t,k] + bv[c]) * zinv[b][t]
    {
        dim3 grid((NB * NT) / 128, NC / 128, 1);   // n = global token, m = channel
        gemm_h<false, true, false, 1, true, true><<<grid, 128, SMEM>>>(
            wT + 2 * NC * NC, xr, bv, zinv, nullptr, vT, nullptr,
            NC, NC, NT, NC, 0, 0, (size_t)NC * NT);
    }

    // 5) read[b][t][v] = sum_s P[b,t,s] * vT[b,v,s]  -> out[..., 512:1024]
    {
        dim3 grid(NC / 128, NT / 128, NB);
        gemm_h<false, false, true, 0, false, false><<<grid, 128, SMEM>>>(
            p, vT, nullptr, nullptr, out + NC, nullptr, nullptr, NT, NT, 2 * NC, NT,
            strLG, (size_t)NC * NT, strOUT);
    }
}